// round 9
// baseline (speedup 1.0000x reference)
#include <cuda_runtime.h>
#include <cuda_bf16.h>
#include <cuda_fp16.h>

#define N_NODES 100000
#define N_EDGES 1600000
#define D 32
#define ED 8
#define FULL 0xffffffffu

// Ping-pong node features (fp32) + fp16 gather copy + per-layer agg buffers.
__device__ float  g_buf0[N_NODES * D];
__device__ float  g_buf1[N_NODES * D];
__device__ __half g_xh[N_NODES * D];      // fp16 copy of current layer input
__device__ float  g_agg[3][N_NODES * D];

// ---------------------------------------------------------------------------
// Once per call: zero all 3 agg buffers AND build the fp16 copy of the
// external input x (layer 0's gather source).
// ---------------------------------------------------------------------------
__global__ void prep_kernel(const float* __restrict__ x) {
    const int tid = blockIdx.x * blockDim.x + threadIdx.x;
    const int nt  = gridDim.x * blockDim.x;

    const int n4 = 3 * N_NODES * D / 4;
    float4* p = reinterpret_cast<float4*>(&g_agg[0][0]);
    float4 z = make_float4(0.f, 0.f, 0.f, 0.f);
    for (int i = tid; i < n4; i += nt) p[i] = z;

    const int nh2 = N_NODES * D / 2;
    __half2* h = reinterpret_cast<__half2*>(g_xh);
    const float2* xf = reinterpret_cast<const float2*>(x);
    for (int i = tid; i < nh2; i += nt) h[i] = __float22half2_rn(xf[i]);
}

// ---------------------------------------------------------------------------
// Edge kernel: 16 edges per warp-iteration (4 independent 4-edge groups)
// + next-tile index prefetch. lane layout: g = lane>>3 edge-in-quad,
// c = lane&7 column quad (cols 4c..4c+3).
// x gathered from the fp16 copy (64B rows -> half the gather wavefronts);
// all arithmetic and the RED.128 scatter stay fp32.
// ---------------------------------------------------------------------------
__global__ __launch_bounds__(128) void edge_kernel(
    int layer,
    const float* __restrict__ edge_attr,
    const float* __restrict__ We,   // layer slice: [8, 32]
    const float* __restrict__ be,   // layer slice: [32]
    const int*   __restrict__ src,
    const int*   __restrict__ dst)
{
    float* agg = &g_agg[layer][0];

    const int lane = threadIdx.x & 31;
    const int c    = lane & 7;
    const int g    = lane >> 3;
    const int wid  = (blockIdx.x * blockDim.x + threadIdx.x) >> 5;
    const int nw   = (gridDim.x * blockDim.x) >> 5;

    float4 wv[ED];
#pragma unroll
    for (int k = 0; k < ED; k++)
        wv[k] = *reinterpret_cast<const float4*>(We + k * D + c * 4);
    const float4 bias = *reinterpret_cast<const float4*>(be + c * 4);

    int e16 = wid * 16;
    if (e16 >= N_EDGES) return;

    int s[4], d[4];
#pragma unroll
    for (int u = 0; u < 4; u++) {
        s[u] = __ldg(src + e16 + u * 4 + g);
        d[u] = __ldg(dst + e16 + u * 4 + g);
    }

    const int stride = nw * 16;
    for (; e16 < N_EDGES; e16 += stride) {
        // 4 independent fp16 gathers (LDG.64: 4 cols = 2 half2 per lane).
        uint2 xr[4];
#pragma unroll
        for (int u = 0; u < 4; u++)
            xr[u] = __ldg(reinterpret_cast<const uint2*>(
                g_xh + (size_t)s[u] * D + c * 4));

        float av[4];
#pragma unroll
        for (int u = 0; u < 4; u++)
            av[u] = __ldg(edge_attr + (size_t)(e16 + u * 4) * ED + lane);

        // Prefetch next tile's indices.
        const int n16 = e16 + stride;
        const int nc  = (n16 < N_EDGES) ? n16 : 0;
        int ns[4], nd[4];
#pragma unroll
        for (int u = 0; u < 4; u++) {
            ns[u] = __ldg(src + nc + u * 4 + g);
            nd[u] = __ldg(dst + nc + u * 4 + g);
        }

        float4 a[4];
#pragma unroll
        for (int u = 0; u < 4; u++) a[u] = bias;
#pragma unroll
        for (int k = 0; k < ED; k++) {
            const float4 wk = wv[k];
#pragma unroll
            for (int u = 0; u < 4; u++) {
                const float f = __shfl_sync(FULL, av[u], (g << 3) | k);
                a[u].x = fmaf(f, wk.x, a[u].x);
                a[u].y = fmaf(f, wk.y, a[u].y);
                a[u].z = fmaf(f, wk.z, a[u].z);
                a[u].w = fmaf(f, wk.w, a[u].w);
            }
        }

#pragma unroll
        for (int u = 0; u < 4; u++) {
            const float2 xlo = __half22float2(
                *reinterpret_cast<const __half2*>(&xr[u].x));
            const float2 xhi = __half22float2(
                *reinterpret_cast<const __half2*>(&xr[u].y));
            float4 m;
            m.x = fmaxf(xlo.x + a[u].x, 0.0f);
            m.y = fmaxf(xlo.y + a[u].y, 0.0f);
            m.z = fmaxf(xhi.x + a[u].z, 0.0f);
            m.w = fmaxf(xhi.y + a[u].w, 0.0f);
            float* p = agg + (size_t)d[u] * D + c * 4;
            asm volatile("red.global.add.v4.f32 [%0], {%1,%2,%3,%4};"
                         :: "l"(p), "f"(m.x), "f"(m.y), "f"(m.z), "f"(m.w)
                         : "memory");
        }

#pragma unroll
        for (int u = 0; u < 4; u++) { s[u] = ns[u]; d[u] = nd[u]; }
    }
}

// ---------------------------------------------------------------------------
// Node kernel: one warp per node. Also writes the fp16 copy of its output
// (the next layer's gather source). Self term stays fully fp32.
// ---------------------------------------------------------------------------
__global__ __launch_bounds__(256) void node_kernel(
    const float* __restrict__ x_ext, int x_sel, int layer,
    float* __restrict__ out_ext, int out_sel,
    const float* __restrict__ W,    // [32, 32]
    const float* __restrict__ b)    // [32]
{
    const float* x  = (x_sel == 0) ? x_ext : (x_sel == 1 ? g_buf0 : g_buf1);
    float* out = (out_sel == 0) ? out_ext : (out_sel == 1 ? g_buf0 : g_buf1);
    const float* agg = &g_agg[layer][0];

    const int lane = threadIdx.x & 31;
    const int wid  = (blockIdx.x * blockDim.x + threadIdx.x) >> 5;
    const int nw   = (gridDim.x * blockDim.x) >> 5;

    float w[D];
#pragma unroll
    for (int k = 0; k < D; k++) w[k] = W[k * D + lane];
    const float bias = b[lane];

    for (int node = wid; node < N_NODES; node += nw) {
        const float h = x[node * D + lane] + agg[node * D + lane];
        float acc = bias;
#pragma unroll
        for (int k = 0; k < D; k++)
            acc = fmaf(__shfl_sync(FULL, h, k), w[k], acc);
        const float o = fmaxf(acc, 0.01f * acc);  // leaky_relu 0.01
        out[node * D + lane] = o;
        g_xh[node * D + lane] = __float2half_rn(o);  // next layer gather copy
    }
}

// ---------------------------------------------------------------------------
extern "C" void kernel_launch(void* const* d_in, const int* in_sizes, int n_in,
                              void* d_out, int out_size)
{
    const float* x   = (const float*)d_in[0];   // [N, 32]
    const float* ea  = (const float*)d_in[1];   // [E, 8]
    const float* W   = (const float*)d_in[2];   // [3, 32, 32]
    const float* b   = (const float*)d_in[3];   // [3, 32]
    const float* We  = (const float*)d_in[4];   // [3, 8, 32]
    const float* be  = (const float*)d_in[5];   // [3, 32]
    const int*   ei  = (const int*)d_in[6];     // [2, E] int32
    float* out = (float*)d_out;

    const int* src = ei;
    const int* dst = ei + N_EDGES;

    const int x_sels[3]   = {0, 1, 2};
    const int out_sels[3] = {1, 2, 0};

    prep_kernel<<<1184, 256>>>(x);
    for (int l = 0; l < 3; l++) {
        edge_kernel<<<2368, 128>>>(
            l, ea, We + l * ED * D, be + l * D, src, dst);
        node_kernel<<<592, 256>>>(
            x, x_sels[l], l, out, out_sels[l], W + l * D * D, b + l * D);
    }
}

// round 10
// speedup vs baseline: 1.1035x; 1.1035x over previous
#include <cuda_runtime.h>
#include <cuda_bf16.h>

#define N_NODES 100000
#define N_EDGES 1600000
#define D 32
#define ED 8
#define FULL 0xffffffffu
#define UN 6                 // 4-edge groups per tile -> 24 edges per warp-iter
#define TILE (UN * 4)

// Ping-pong node features + per-layer aggregation buffers (zeroed once).
__device__ float g_buf0[N_NODES * D];
__device__ float g_buf1[N_NODES * D];
__device__ float g_agg[3][N_NODES * D];

// ---------------------------------------------------------------------------
// Zero ALL three aggregation buffers in one pass (runs once per call).
// ---------------------------------------------------------------------------
__global__ void zero_all_kernel() {
    const int n4 = 3 * N_NODES * D / 4;
    float4* p = reinterpret_cast<float4*>(&g_agg[0][0]);
    float4 z = make_float4(0.f, 0.f, 0.f, 0.f);
    for (int i = blockIdx.x * blockDim.x + threadIdx.x; i < n4;
         i += gridDim.x * blockDim.x) {
        p[i] = z;
    }
}

// ---------------------------------------------------------------------------
// Edge kernel: 24 edges per warp-iteration (6 independent 4-edge groups)
// + next-tile index prefetch + consolidated lane-indexed idx loads.
//   lane layout: g = lane>>3 edge-in-quad, c = lane&7 column quad (4c..4c+3).
// Per tile: 6 independent x-gather LDG.128 + 6 RED.128 in flight (MLP=6);
// src/dst indices come from 2 lane-indexed LDG.32 + SHFL extraction.
// ---------------------------------------------------------------------------
__global__ __launch_bounds__(128) void edge_kernel(
    const float* __restrict__ x_ext, int x_sel, int layer,
    const float* __restrict__ edge_attr,
    const float* __restrict__ We,   // layer slice: [8, 32]
    const float* __restrict__ be,   // layer slice: [32]
    const int*   __restrict__ src,
    const int*   __restrict__ dst)
{
    const float* x = (x_sel == 0) ? x_ext : (x_sel == 1 ? g_buf0 : g_buf1);
    float* agg = &g_agg[layer][0];

    const int lane = threadIdx.x & 31;
    const int c    = lane & 7;
    const int g    = lane >> 3;
    const int wid  = (blockIdx.x * blockDim.x + threadIdx.x) >> 5;
    const int nw   = (gridDim.x * blockDim.x) >> 5;

    float4 wv[ED];
#pragma unroll
    for (int k = 0; k < ED; k++)
        wv[k] = *reinterpret_cast<const float4*>(We + k * D + c * 4);
    const float4 bias = *reinterpret_cast<const float4*>(be + c * 4);

    int e = wid * TILE;
    if (e >= N_EDGES) return;

    // Lane j (clamped to tile width) owns index slot j of each tile.
    const int jl = (lane < TILE) ? lane : (TILE - 1);

    // Prologue: first tile's 24 src + 24 dst ids in two lane-indexed loads.
    int is = __ldg(src + min(e + jl, N_EDGES - 1));
    int id = __ldg(dst + min(e + jl, N_EDGES - 1));

    const int stride = nw * TILE;
    for (; e < N_EDGES; e += stride) {
        // Extract src ids and issue 6 independent gathers immediately.
        float4 xv[UN];
#pragma unroll
        for (int u = 0; u < UN; u++) {
            const int s = __shfl_sync(FULL, is, u * 4 + g);
            xv[u] = __ldg(reinterpret_cast<const float4*>(
                x + (size_t)s * D + c * 4));
        }

        // Attr loads (chain-free; address clamped so tail groups stay in-bounds).
        float av[UN];
#pragma unroll
        for (int u = 0; u < UN; u++) {
            const int ec = min(e + u * 4, N_EDGES - 4);
            av[u] = __ldg(edge_attr + (size_t)ec * ED + lane);
        }

        // Prefetch next tile's indices.
        const int ne = e + stride;
        const int nc = (ne < N_EDGES) ? ne : 0;
        const int nis = __ldg(src + min(nc + jl, N_EDGES - 1));
        const int nid = __ldg(dst + min(nc + jl, N_EDGES - 1));

        // Extract dst ids (cheap SHFLs, no memory dependency).
        int dd[UN];
#pragma unroll
        for (int u = 0; u < UN; u++)
            dd[u] = __shfl_sync(FULL, id, u * 4 + g);

        float4 a[UN];
#pragma unroll
        for (int u = 0; u < UN; u++) a[u] = bias;
#pragma unroll
        for (int k = 0; k < ED; k++) {
            const float4 wk = wv[k];
#pragma unroll
            for (int u = 0; u < UN; u++) {
                const float f = __shfl_sync(FULL, av[u], (g << 3) | k);
                a[u].x = fmaf(f, wk.x, a[u].x);
                a[u].y = fmaf(f, wk.y, a[u].y);
                a[u].z = fmaf(f, wk.z, a[u].z);
                a[u].w = fmaf(f, wk.w, a[u].w);
            }
        }

#pragma unroll
        for (int u = 0; u < UN; u++) {
            if (e + u * 4 + g < N_EDGES) {   // tail guard (groups are 4-aligned)
                float4 m;
                m.x = fmaxf(xv[u].x + a[u].x, 0.0f);
                m.y = fmaxf(xv[u].y + a[u].y, 0.0f);
                m.z = fmaxf(xv[u].z + a[u].z, 0.0f);
                m.w = fmaxf(xv[u].w + a[u].w, 0.0f);
                float* p = agg + (size_t)dd[u] * D + c * 4;
                asm volatile("red.global.add.v4.f32 [%0], {%1,%2,%3,%4};"
                             :: "l"(p), "f"(m.x), "f"(m.y), "f"(m.z), "f"(m.w)
                             : "memory");
            }
        }

        is = nis;
        id = nid;
    }
}

// ---------------------------------------------------------------------------
// Node kernel: one warp per node (fp32 only; R8 form).
// ---------------------------------------------------------------------------
__global__ __launch_bounds__(256) void node_kernel(
    const float* __restrict__ x_ext, int x_sel, int layer,
    float* __restrict__ out_ext, int out_sel,
    const float* __restrict__ W,    // [32, 32]
    const float* __restrict__ b)    // [32]
{
    const float* x  = (x_sel == 0) ? x_ext : (x_sel == 1 ? g_buf0 : g_buf1);
    float* out = (out_sel == 0) ? out_ext : (out_sel == 1 ? g_buf0 : g_buf1);
    const float* agg = &g_agg[layer][0];

    const int lane = threadIdx.x & 31;
    const int wid  = (blockIdx.x * blockDim.x + threadIdx.x) >> 5;
    const int nw   = (gridDim.x * blockDim.x) >> 5;

    float w[D];
#pragma unroll
    for (int k = 0; k < D; k++) w[k] = W[k * D + lane];
    const float bias = b[lane];

    for (int node = wid; node < N_NODES; node += nw) {
        const float h = x[node * D + lane] + agg[node * D + lane];
        float acc = bias;
#pragma unroll
        for (int k = 0; k < D; k++)
            acc = fmaf(__shfl_sync(FULL, h, k), w[k], acc);
        out[node * D + lane] = fmaxf(acc, 0.01f * acc);  // leaky_relu 0.01
    }
}

// ---------------------------------------------------------------------------
extern "C" void kernel_launch(void* const* d_in, const int* in_sizes, int n_in,
                              void* d_out, int out_size)
{
    const float* x   = (const float*)d_in[0];   // [N, 32]
    const float* ea  = (const float*)d_in[1];   // [E, 8]
    const float* W   = (const float*)d_in[2];   // [3, 32, 32]
    const float* b   = (const float*)d_in[3];   // [3, 32]
    const float* We  = (const float*)d_in[4];   // [3, 8, 32]
    const float* be  = (const float*)d_in[5];   // [3, 32]
    const int*   ei  = (const int*)d_in[6];     // [2, E] int32
    float* out = (float*)d_out;

    const int* src = ei;
    const int* dst = ei + N_EDGES;

    const int x_sels[3]   = {0, 1, 2};
    const int out_sels[3] = {1, 2, 0};

    zero_all_kernel<<<1184, 256>>>();
    for (int l = 0; l < 3; l++) {
        edge_kernel<<<2368, 128>>>(
            x, x_sels[l], l, ea, We + l * ED * D, be + l * D, src, dst);
        node_kernel<<<592, 256>>>(
            x, x_sels[l], l, out, out_sels[l], W + l * D * D, b + l * D);
    }
}